// round 14
// baseline (speedup 1.0000x reference)
#include <cuda_runtime.h>
#include <cuda_bf16.h>

// GaussianKernelLoss: B=32, N=16, H=W=256, SIGMA=0.1, RADIUS=0.2
// d_in[0]=pred [32,16,2] f32, d_in[1]=target [32,16,2] f32,
// d_in[2]=visibility [32,16] f32, d_in[3]=coord_grid [2,256,256] f32 (linspace i/255)
// Output: scalar f32.

#define BN     512
#define RADIUS 0.2f
#define R2     (0.2f * 0.2f)
#define COEF   (-50.0f)        // -1/(2*sigma^2)
#define INV255 (1.0f / 255.0f)
#define NCOL   4               // 4*32 = 128 >= max bbox width (<=104)
#define NTHR   256             // 8 warps per block, 1 landmark per block

__device__ __align__(16) float gQ[BN];  // per-landmark quotients (spread stores)
__device__ int g_count;                 // zero-init; last block resets each launch

__global__ __launch_bounds__(NTHR)
void gkl_fused_kernel(const float* __restrict__ pred,
                      const float* __restrict__ tgt,
                      const float* __restrict__ vis,
                      const float* __restrict__ grid,
                      float* __restrict__ out)
{
    const int lm  = blockIdx.x;
    const int tid = threadIdx.x;
    const int cx  = tid & 31;   // lane -> column subset
    const int cy  = tid >> 5;   // warp (0..7) -> row residue (stride 8)

    __shared__ float redN[8], redD[8];

    // Issue all three input loads back-to-back so their latencies overlap.
    const float  v   = vis[lm];
    const float2 t2v = ((const float2*)tgt)[lm];
    const float2 p2v = ((const float2*)pred)[lm];

    float num0 = 0.0f, den0 = 0.0f;     // two independent accumulator chains
    float num1 = 0.0f, den1 = 0.0f;

    if (v >= 0.5f) {
        const float tx = t2v.x, ty = t2v.y;
        const float px = p2v.x, py = p2v.y;

        // Bbox via truncation: trunc != floor only for negatives, where the
        // max(0,·) clamp absorbs the difference; x0u+103 provably covers
        // ceil((t+R)*255) since the disk diameter is exactly 102 px.
        const int x0u = (int)fmaf(tx, 255.0f, -51.0f);
        const int y0u = (int)fmaf(ty, 255.0f, -51.0f);
        const int x0 = max(0, x0u), x1 = min(255, x0u + 103);
        const int y0 = max(0, y0u), y1 = min(255, y0u + 103);
        const int bw = x1 - x0 + 1;
        const int bh = y1 - y0 + 1;

        // Column tables in registers: lane cx owns columns cx + 32k.
        // Out-of-range columns poisoned (Ex=0, T2=huge) -> contribute 0.
        float cT2[NCOL], cP2[NCOL], cEx[NCOL];
        #pragma unroll
        for (int k = 0; k < NCOL; k++) {
            const int j   = cx + 32 * k;
            const bool ok = (j < bw);
            const float xv = (float)(x0 + j) * INV255;   // coord_grid == linspace
            const float dt = xv - tx;
            const float dp = xv - px;
            cT2[k] = ok ? dt * dt : 1e9f;
            cP2[k] = dp * dp;
            cEx[k] = ok ? __expf(COEF * dt * dt) : 0.0f;
        }

        // Incremental row coordinates: chain A = rows cy+16n, chain B = rows
        // cy+8+16n; both advanced by 16*INV255 per iteration (stride-8 overall).
        const float base = (float)y0 * INV255;
        float dtyA = fmaf((float)cy,       INV255, base - ty);
        float dpyA = fmaf((float)cy,       INV255, base - py);
        float dtyB = fmaf((float)(cy + 8), INV255, base - ty);
        float dpyB = fmaf((float)(cy + 8), INV255, base - py);
        const float STEP = 16.0f * INV255;

        int i = cy;
        for (; i + 8 < bh; i += 16) {
            {   // row i (chain A)
                const float t2y = dtyA * dtyA;
                const float p2y = dpyA * dpyA;
                const float ey  = __expf(COEF * t2y);
                const float lim = R2 - t2y;
                #pragma unroll
                for (int k = 0; k < NCOL; k++) {
                    const float d2p = cP2[k] + p2y;
                    const float w   = cEx[k] * ey;
                    float d;
                    asm("sqrt.approx.f32 %0, %1;" : "=f"(d) : "f"(d2p));
                    if (cT2[k] <= lim) {
                        num0 = fmaf(w, d, num0);
                        den0 += w;
                    }
                }
                dtyA += STEP; dpyA += STEP;
            }
            {   // row i+8 (chain B)
                const float t2y = dtyB * dtyB;
                const float p2y = dpyB * dpyB;
                const float ey  = __expf(COEF * t2y);
                const float lim = R2 - t2y;
                #pragma unroll
                for (int k = 0; k < NCOL; k++) {
                    const float d2p = cP2[k] + p2y;
                    const float w   = cEx[k] * ey;
                    float d;
                    asm("sqrt.approx.f32 %0, %1;" : "=f"(d) : "f"(d2p));
                    if (cT2[k] <= lim) {
                        num1 = fmaf(w, d, num1);
                        den1 += w;
                    }
                }
                dtyB += STEP; dpyB += STEP;
            }
        }
        if (i < bh) {   // remainder row (chain A)
            const float t2y = dtyA * dtyA;
            const float p2y = dpyA * dpyA;
            const float ey  = __expf(COEF * t2y);
            const float lim = R2 - t2y;
            #pragma unroll
            for (int k = 0; k < NCOL; k++) {
                const float d2p = cP2[k] + p2y;
                const float w   = cEx[k] * ey;
                float d;
                asm("sqrt.approx.f32 %0, %1;" : "=f"(d) : "f"(d2p));
                if (cT2[k] <= lim) {
                    num0 = fmaf(w, d, num0);
                    den0 += w;
                }
            }
        }
    }

    float num = num0 + num1;
    float den = den0 + den1;

    // Block reduction (8 warps) — uniform path for all blocks.
    #pragma unroll
    for (int o = 16; o; o >>= 1) {
        num += __shfl_xor_sync(0xffffffffu, num, o);
        den += __shfl_xor_sync(0xffffffffu, den, o);
    }
    if (cx == 0) { redN[cy] = num; redD[cy] = den; }
    __syncthreads();

    // Warp 0 finishes: quotient store, arrival, and (if last) the scalar fold.
    // Warps 1..7 exit here.
    if (cy == 0) {
        int last = 0;
        if (cx == 0) {
            float n = 0.0f, d = 0.0f;
            #pragma unroll
            for (int k = 0; k < 8; k++) { n += redN[k]; d += redD[k]; }
            gQ[lm] = n / (d + 1e-8f);   // invisible: 0/1e-8 = 0
            __threadfence();
            last = (atomicAdd(&g_count, 1) == BN - 1);
        }
        last = __shfl_sync(0xffffffffu, last, 0);

        if (last) {
            __threadfence();            // acquire side of the arrival
            // Lane cx owns gQ[16cx .. 16cx+15]: 4 independent float4 loads
            // (one memory latency), pairwise-tree fold, then warp reduce.
            const float4* q4 = (const float4*)&gQ[cx * 16];
            const float4 a = __ldcg(q4 + 0);
            const float4 b = __ldcg(q4 + 1);
            const float4 c = __ldcg(q4 + 2);
            const float4 e = __ldcg(q4 + 3);
            const float s0 = (a.x + a.y) + (a.z + a.w);
            const float s1 = (b.x + b.y) + (b.z + b.w);
            const float s2 = (c.x + c.y) + (c.z + c.w);
            const float s3 = (e.x + e.y) + (e.z + e.w);
            float s = (s0 + s1) + (s2 + s3);
            #pragma unroll
            for (int o = 16; o; o >>= 1) s += __shfl_xor_sync(0xffffffffu, s, o);
            if (cx == 0) {
                *out = s / (512.0f + 1e-8f);
                g_count = 0;            // reset for next graph replay
            }
        }
    }
}

extern "C" void kernel_launch(void* const* d_in, const int* in_sizes, int n_in,
                              void* d_out, int out_size)
{
    const float* pred = (const float*)d_in[0];
    const float* tgt  = (const float*)d_in[1];
    const float* vis  = (const float*)d_in[2];
    const float* grid = (const float*)d_in[3];
    gkl_fused_kernel<<<BN, NTHR>>>(pred, tgt, vis, grid, (float*)d_out);
}

// round 15
// speedup vs baseline: 1.0260x; 1.0260x over previous
#include <cuda_runtime.h>
#include <cuda_bf16.h>

// GaussianKernelLoss: B=32, N=16, H=W=256, SIGMA=0.1, RADIUS=0.2
// d_in[0]=pred [32,16,2] f32, d_in[1]=target [32,16,2] f32,
// d_in[2]=visibility [32,16] f32, d_in[3]=coord_grid [2,256,256] f32 (linspace i/255)
// Output: scalar f32.

#define BN     512
#define RADIUS 0.2f
#define R2     (0.2f * 0.2f)
#define COEF   (-50.0f)        // -1/(2*sigma^2)
#define INV255 (1.0f / 255.0f)
#define NCOL   4               // 4*32 = 128 >= max bbox width (<=104 exact)
#define NTHR   256             // 8 warps per block, 1 landmark per block

__device__ float gQ[BN];       // per-landmark quotients (spread stores, no chain)
__device__ int   g_count;      // zero-init; last block resets each launch

__global__ __launch_bounds__(NTHR)
void gkl_fused_kernel(const float* __restrict__ pred,
                      const float* __restrict__ tgt,
                      const float* __restrict__ vis,
                      const float* __restrict__ grid,
                      float* __restrict__ out)
{
    const int lm  = blockIdx.x;
    const int tid = threadIdx.x;
    const int cx  = tid & 31;   // lane -> column subset
    const int cy  = tid >> 5;   // warp (0..7) -> row residue (stride 8)

    __shared__ float redN[8], redD[8];
    __shared__ int   sIsLast;

    // Issue all three input loads back-to-back so their latencies overlap.
    const float  v   = vis[lm];
    const float2 t2v = ((const float2*)tgt)[lm];
    const float2 p2v = ((const float2*)pred)[lm];

    float num0 = 0.0f, den0 = 0.0f;     // two independent accumulator chains
    float num1 = 0.0f, den1 = 0.0f;

    if (v >= 0.5f) {
        const float tx = t2v.x, ty = t2v.y;
        const float px = p2v.x, py = p2v.y;

        // Exact bounding box of the radius disk (per-pixel mask is exact).
        const int x0 = max(0,   (int)floorf((tx - RADIUS) * 255.0f));
        const int y0 = max(0,   (int)floorf((ty - RADIUS) * 255.0f));
        const int x1 = min(255, (int)ceilf ((tx + RADIUS) * 255.0f));
        const int y1 = min(255, (int)ceilf ((ty + RADIUS) * 255.0f));
        const int bw = x1 - x0 + 1;
        const int bh = y1 - y0 + 1;

        // Column tables in registers: lane cx owns columns cx + 32k.
        // Out-of-range columns poisoned (Ex=0, T2=huge) -> contribute 0.
        float cT2[NCOL], cP2[NCOL], cEx[NCOL];
        #pragma unroll
        for (int k = 0; k < NCOL; k++) {
            const int j   = cx + 32 * k;
            const bool ok = (j < bw);
            const float xv = (float)(x0 + j) * INV255;   // coord_grid == linspace
            const float dt = xv - tx;
            const float dp = xv - px;
            cT2[k] = ok ? dt * dt : 1e9f;
            cP2[k] = dp * dp;
            cEx[k] = ok ? __expf(COEF * dt * dt) : 0.0f;
        }

        // Incremental row coordinates: chain A = rows cy+16n, chain B = rows
        // cy+8+16n; both advanced by 16*INV255 per iteration (stride-8 overall).
        const float base = (float)y0 * INV255;
        float dtyA = fmaf((float)cy,       INV255, base - ty);
        float dpyA = fmaf((float)cy,       INV255, base - py);
        float dtyB = fmaf((float)(cy + 8), INV255, base - ty);
        float dpyB = fmaf((float)(cy + 8), INV255, base - py);
        const float STEP = 16.0f * INV255;

        int i = cy;
        for (; i + 8 < bh; i += 16) {
            {   // row i (chain A)
                const float t2y = dtyA * dtyA;
                const float p2y = dpyA * dpyA;
                const float ey  = __expf(COEF * t2y);
                const float lim = R2 - t2y;
                #pragma unroll
                for (int k = 0; k < NCOL; k++) {
                    const float d2p = cP2[k] + p2y;
                    const float w   = cEx[k] * ey;
                    float d;
                    asm("sqrt.approx.f32 %0, %1;" : "=f"(d) : "f"(d2p));
                    if (cT2[k] <= lim) {
                        num0 = fmaf(w, d, num0);
                        den0 += w;
                    }
                }
                dtyA += STEP; dpyA += STEP;
            }
            {   // row i+8 (chain B)
                const float t2y = dtyB * dtyB;
                const float p2y = dpyB * dpyB;
                const float ey  = __expf(COEF * t2y);
                const float lim = R2 - t2y;
                #pragma unroll
                for (int k = 0; k < NCOL; k++) {
                    const float d2p = cP2[k] + p2y;
                    const float w   = cEx[k] * ey;
                    float d;
                    asm("sqrt.approx.f32 %0, %1;" : "=f"(d) : "f"(d2p));
                    if (cT2[k] <= lim) {
                        num1 = fmaf(w, d, num1);
                        den1 += w;
                    }
                }
                dtyB += STEP; dpyB += STEP;
            }
        }
        if (i < bh) {   // remainder row (chain A)
            const float t2y = dtyA * dtyA;
            const float p2y = dpyA * dpyA;
            const float ey  = __expf(COEF * t2y);
            const float lim = R2 - t2y;
            #pragma unroll
            for (int k = 0; k < NCOL; k++) {
                const float d2p = cP2[k] + p2y;
                const float w   = cEx[k] * ey;
                float d;
                asm("sqrt.approx.f32 %0, %1;" : "=f"(d) : "f"(d2p));
                if (cT2[k] <= lim) {
                    num0 = fmaf(w, d, num0);
                    den0 += w;
                }
            }
        }
    }

    float num = num0 + num1;
    float den = den0 + den1;

    // Block reduction (8 warps) — uniform path for all blocks.
    #pragma unroll
    for (int o = 16; o; o >>= 1) {
        num += __shfl_xor_sync(0xffffffffu, num, o);
        den += __shfl_xor_sync(0xffffffffu, den, o);
    }
    if (cx == 0) { redN[cy] = num; redD[cy] = den; }
    __syncthreads();

    if (tid == 0) {
        float n = 0.0f, d = 0.0f;
        #pragma unroll
        for (int k = 0; k < 8; k++) { n += redN[k]; d += redD[k]; }
        gQ[lm] = n / (d + 1e-8f);      // invisible: 0/1e-8 = 0 (off the tail path)
        // Single acq_rel RMW replaces threadfence(release) + relaxed atomic +
        // threadfence(acquire): release publishes the gQ store; acquire on the
        // winning arrival makes all published gQ visible to the fold below.
        int c;
        asm volatile("atom.acq_rel.gpu.global.add.s32 %0, [%1], %2;"
                     : "=r"(c) : "l"(&g_count), "r"(1) : "memory");
        sIsLast = (c == BN - 1);
    }
    __syncthreads();

    // Last block folds the 512 quotients into the scalar output.
    if (sIsLast) {
        float s = __ldcg(&gQ[tid]) + __ldcg(&gQ[tid + 256]);
        #pragma unroll
        for (int o = 16; o; o >>= 1) s += __shfl_xor_sync(0xffffffffu, s, o);
        if (cx == 0) redN[cy] = s;
        __syncthreads();
        if (tid == 0) {
            float t = 0.0f;
            #pragma unroll
            for (int k = 0; k < 8; k++) t += redN[k];
            *out = t / (512.0f + 1e-8f);
            g_count = 0;                        // reset for next graph replay
        }
    }
}

extern "C" void kernel_launch(void* const* d_in, const int* in_sizes, int n_in,
                              void* d_out, int out_size)
{
    const float* pred = (const float*)d_in[0];
    const float* tgt  = (const float*)d_in[1];
    const float* vis  = (const float*)d_in[2];
    const float* grid = (const float*)d_in[3];
    gkl_fused_kernel<<<BN, NTHR>>>(pred, tgt, vis, grid, (float*)d_out);
}

// round 17
// speedup vs baseline: 1.0661x; 1.0390x over previous
#include <cuda_runtime.h>
#include <cuda_bf16.h>

// GaussianKernelLoss: B=32, N=16, H=W=256, SIGMA=0.1, RADIUS=0.2
// d_in[0]=pred [32,16,2] f32, d_in[1]=target [32,16,2] f32,
// d_in[2]=visibility [32,16] f32, d_in[3]=coord_grid [2,256,256] f32 (linspace i/255)
// Output: scalar f32.

#define BN     512
#define RADIUS 0.2f
#define R2     (0.2f * 0.2f)
#define COEF   (-50.0f)        // -1/(2*sigma^2)
#define INV255 (1.0f / 255.0f)
#define NCOL   4               // 4*32 = 128 >= max bbox width (<=104 exact)
#define NTHR   256             // 8 warps per block, 1 landmark per block

__device__ float gQ[BN];       // per-landmark quotients (spread stores, no chain)
__device__ int   g_count;      // zero-init; last block resets each launch

__global__ __launch_bounds__(NTHR)
void gkl_fused_kernel(const float* __restrict__ pred,
                      const float* __restrict__ tgt,
                      const float* __restrict__ vis,
                      const float* __restrict__ grid,
                      float* __restrict__ out)
{
    const int lm  = blockIdx.x;
    const int tid = threadIdx.x;
    const int cx  = tid & 31;   // lane -> column subset
    const int cy  = tid >> 5;   // warp (0..7) -> row residue (stride 8)

    __shared__ float redN[8], redD[8];
    __shared__ int   sIsLast;

    // Issue all three input loads back-to-back so their latencies overlap.
    const float  v   = vis[lm];
    const float2 t2v = ((const float2*)tgt)[lm];
    const float2 p2v = ((const float2*)pred)[lm];

    float num0 = 0.0f, den0 = 0.0f;     // two independent accumulator chains
    float num1 = 0.0f, den1 = 0.0f;

    if (v >= 0.5f) {
        const float tx = t2v.x, ty = t2v.y;
        const float px = p2v.x, py = p2v.y;

        // Exact bounding box of the radius disk (per-pixel mask is exact).
        const int x0 = max(0,   (int)floorf((tx - RADIUS) * 255.0f));
        const int y0 = max(0,   (int)floorf((ty - RADIUS) * 255.0f));
        const int x1 = min(255, (int)ceilf ((tx + RADIUS) * 255.0f));
        const int y1 = min(255, (int)ceilf ((ty + RADIUS) * 255.0f));
        const int bw = x1 - x0 + 1;
        const int bh = y1 - y0 + 1;

        // Column tables in registers: lane cx owns columns cx + 32k.
        // Out-of-range columns poisoned (Ex=0, T2=huge) -> contribute 0.
        float cT2[NCOL], cP2[NCOL], cEx[NCOL];
        #pragma unroll
        for (int k = 0; k < NCOL; k++) {
            const int j   = cx + 32 * k;
            const bool ok = (j < bw);
            const float xv = (float)(x0 + j) * INV255;   // coord_grid == linspace
            const float dt = xv - tx;
            const float dp = xv - px;
            cT2[k] = ok ? dt * dt : 1e9f;
            cP2[k] = dp * dp;
            cEx[k] = ok ? __expf(COEF * dt * dt) : 0.0f;
        }

        // Incremental row coordinates: chain A = rows cy+16n, chain B = rows
        // cy+8+16n; both advanced by 16*INV255 per iteration (stride-8 overall).
        const float base = (float)y0 * INV255;
        float dtyA = fmaf((float)cy,       INV255, base - ty);
        float dpyA = fmaf((float)cy,       INV255, base - py);
        float dtyB = fmaf((float)(cy + 8), INV255, base - ty);
        float dpyB = fmaf((float)(cy + 8), INV255, base - py);
        const float STEP = 16.0f * INV255;

        int i = cy;
        for (; i + 8 < bh; i += 16) {
            {   // row i (chain A)
                const float t2y = dtyA * dtyA;
                const float p2y = dpyA * dpyA;
                const float ey  = __expf(COEF * t2y);
                const float lim = R2 - t2y;
                #pragma unroll
                for (int k = 0; k < NCOL; k++) {
                    const float d2p = cP2[k] + p2y;
                    const float w   = cEx[k] * ey;
                    float d;
                    asm("sqrt.approx.f32 %0, %1;" : "=f"(d) : "f"(d2p));
                    if (cT2[k] <= lim) {
                        num0 = fmaf(w, d, num0);
                        den0 += w;
                    }
                }
                dtyA += STEP; dpyA += STEP;
            }
            {   // row i+8 (chain B)
                const float t2y = dtyB * dtyB;
                const float p2y = dpyB * dpyB;
                const float ey  = __expf(COEF * t2y);
                const float lim = R2 - t2y;
                #pragma unroll
                for (int k = 0; k < NCOL; k++) {
                    const float d2p = cP2[k] + p2y;
                    const float w   = cEx[k] * ey;
                    float d;
                    asm("sqrt.approx.f32 %0, %1;" : "=f"(d) : "f"(d2p));
                    if (cT2[k] <= lim) {
                        num1 = fmaf(w, d, num1);
                        den1 += w;
                    }
                }
                dtyB += STEP; dpyB += STEP;
            }
        }
        if (i < bh) {   // remainder row (chain A)
            const float t2y = dtyA * dtyA;
            const float p2y = dpyA * dpyA;
            const float ey  = __expf(COEF * t2y);
            const float lim = R2 - t2y;
            #pragma unroll
            for (int k = 0; k < NCOL; k++) {
                const float d2p = cP2[k] + p2y;
                const float w   = cEx[k] * ey;
                float d;
                asm("sqrt.approx.f32 %0, %1;" : "=f"(d) : "f"(d2p));
                if (cT2[k] <= lim) {
                    num0 = fmaf(w, d, num0);
                    den0 += w;
                }
            }
        }
    }

    float num = num0 + num1;
    float den = den0 + den1;

    // Block reduction (8 warps) — uniform path for all blocks.
    #pragma unroll
    for (int o = 16; o; o >>= 1) {
        num += __shfl_xor_sync(0xffffffffu, num, o);
        den += __shfl_xor_sync(0xffffffffu, den, o);
    }
    if (cx == 0) { redN[cy] = num; redD[cy] = den; }
    __syncthreads();

    if (tid == 0) {
        float n = 0.0f, d = 0.0f;
        #pragma unroll
        for (int k = 0; k < 8; k++) { n += redN[k]; d += redD[k]; }
        gQ[lm] = n / (d + 1e-8f);      // invisible: 0/1e-8 = 0 (off the tail path)
        // Single acq_rel RMW replaces threadfence(release) + relaxed atomic +
        // threadfence(acquire): release publishes the gQ store; acquire on the
        // winning arrival makes all published gQ visible to the fold below.
        int c;
        asm volatile("atom.acq_rel.gpu.global.add.s32 %0, [%1], %2;"
                     : "=r"(c) : "l"(&g_count), "r"(1) : "memory");
        sIsLast = (c == BN - 1);
    }
    __syncthreads();

    // Last block folds the 512 quotients into the scalar output.
    if (sIsLast) {
        float s = __ldcg(&gQ[tid]) + __ldcg(&gQ[tid + 256]);
        #pragma unroll
        for (int o = 16; o; o >>= 1) s += __shfl_xor_sync(0xffffffffu, s, o);
        if (cx == 0) redN[cy] = s;
        __syncthreads();
        if (tid == 0) {
            float t = 0.0f;
            #pragma unroll
            for (int k = 0; k < 8; k++) t += redN[k];
            *out = t / (512.0f + 1e-8f);
            g_count = 0;                        // reset for next graph replay
        }
    }
}

extern "C" void kernel_launch(void* const* d_in, const int* in_sizes, int n_in,
                              void* d_out, int out_size)
{
    const float* pred = (const float*)d_in[0];
    const float* tgt  = (const float*)d_in[1];
    const float* vis  = (const float*)d_in[2];
    const float* grid = (const float*)d_in[3];
    gkl_fused_kernel<<<BN, NTHR>>>(pred, tgt, vis, grid, (float*)d_out);
}